// round 9
// baseline (speedup 1.0000x reference)
#include <cuda_runtime.h>
#include <cuda_fp16.h>
#include <cstdint>

#define N_PTS 131072
#define DIM   64
#define KCENT 1024
#define TH_GAP 0.35f

#define ROWS_BLK 128
#define ASSIGN_BLOCKS (N_PTS / ROWS_BLK)   // 1024
#define CHUNKS 8                            // K chunks of 128 cols

// ---------------- device scratch (no allocation allowed) --------------------
__device__ float g_csq[KCENT];
__device__ int   g_ind[N_PTS];
__device__ int   g_counts[KCENT];
__device__ float g_csum[KCENT * DIM];
__device__ float g_cnew[KCENT * DIM];
__device__ float g_loss;
__device__ float g_sum_cs;
__device__ int   g_nflag;
__device__ int   g_flag[N_PTS];
__device__ float g_Ct[KCENT * DIM];                        // C^T for recheck
__device__ __align__(16) __half2 gXh[ASSIGN_BLOCKS * 64 * 64];  // 16.8MB [blk][d][r2]
__device__ __align__(16) __half2 gBh[CHUNKS * 64 * 128];        // 256KB  [cc][d][col] dup

// ---------------- small kernels -----------------------------------------------
__global__ void zero_kernel() {
    int i = blockIdx.x * blockDim.x + threadIdx.x;
    if (i < KCENT * DIM) g_csum[i] = 0.0f;
    if (i < KCENT)       g_counts[i] = 0;
    if (i == 0)          { g_loss = 0.0f; g_nflag = 0; }
}

__global__ void csq_kernel(const float* __restrict__ C) {
    int k = blockIdx.x * blockDim.x + threadIdx.x;
    if (k < KCENT) {
        float s = 0.0f;
        #pragma unroll
        for (int d = 0; d < DIM; d++) {
            float c = C[d * KCENT + k];
            s = fmaf(c, c, s);
        }
        g_csq[k] = s;
    }
}

__global__ void sumcs_kernel(const float* __restrict__ cluster_size) {
    __shared__ float red[1024];
    int k = threadIdx.x;
    red[k] = cluster_size[k];
    __syncthreads();
    #pragma unroll
    for (int s = 512; s > 0; s >>= 1) {
        if (k < s) red[k] += red[k + s];
        __syncthreads();
    }
    if (k == 0) g_sum_cs = red[0];
}

// transpose C [64][1024] -> Ct [1024][64] (for exact recheck)
__global__ void prep_Ct(const float* __restrict__ C) {
    __shared__ float t[32][33];
    int tx = threadIdx.x & 31;
    int ty0 = threadIdx.x >> 5;
    int kb = blockIdx.x * 32;
    int db = blockIdx.y * 32;
    #pragma unroll
    for (int yy = 0; yy < 4; yy++) {
        int ty = ty0 + yy * 8;
        t[ty][tx] = C[(db + ty) * KCENT + kb + tx];
    }
    __syncthreads();
    #pragma unroll
    for (int yy = 0; yy < 4; yy++) {
        int ty = ty0 + yy * 8;
        g_Ct[(kb + ty) * DIM + db + tx] = t[tx][ty];
    }
}

// X -> half2 image [blk][d][r2]: pair (row 2*r2, row 2*r2+1) at dim d
__global__ void prep_Xh(const float* __restrict__ X) {
    __shared__ float xs[64 * 132];
    const int tid = threadIdx.x;
    const int b = blockIdx.x;
    const float4* Xv = reinterpret_cast<const float4*>(X + (size_t)b * ROWS_BLK * DIM);
    #pragma unroll
    for (int j = 0; j < 8; j++) {
        int f = tid + j * 256;          // f < 2048
        float4 v = Xv[f];
        int r = f >> 4;
        int d = (f & 15) * 4;
        xs[(d + 0) * 132 + r] = v.x;
        xs[(d + 1) * 132 + r] = v.y;
        xs[(d + 2) * 132 + r] = v.z;
        xs[(d + 3) * 132 + r] = v.w;
    }
    __syncthreads();
    #pragma unroll
    for (int j = 0; j < 16; j++) {
        int f = tid + j * 256;          // f < 4096
        int d = f >> 6, r2 = f & 63;
        gXh[(size_t)b * 4096 + f] =
            __floats2half2_rn(xs[d * 132 + 2 * r2], xs[d * 132 + 2 * r2 + 1]);
    }
}

// C -> duplicated half2 image [cc][d][col]: (c, c)
__global__ void prep_Bh(const float* __restrict__ C) {
    int i = blockIdx.x * blockDim.x + threadIdx.x;
    if (i >= CHUNKS * 64 * 128) return;
    int col = i & 127;
    int d   = (i >> 7) & 63;
    int cc  = i >> 13;
    gBh[i] = __float2half2_rn(C[d * KCENT + cc * 128 + col]);
}

// ---------------- assign: pure-HFMA2 GEMM + top-2 argmax + fused segsum ------
// smem layout (bytes): xh[64*68 half2]=17408 | cs[64*132 half2]=33792 |
//                      csq[1024f]=4096 | ind[128]=512 | flg[128]=512  => 56320
#define SM_XH   0
#define SM_CS   17408
#define SM_CSQ  51200
#define SM_IND  55296
#define SM_FLG  55808
#define SM_BYTES 56320

__global__ void __launch_bounds__(256, 2)
assign_kernel(const float* __restrict__ X) {
    extern __shared__ __align__(16) unsigned char smraw[];
    __half2* xh    = (__half2*)(smraw + SM_XH);    // [d][r2], pad 68
    __half2* cs    = (__half2*)(smraw + SM_CS);    // [d][col], pad 132
    float*   s_csq = (float*)(smraw + SM_CSQ);
    int*     s_ind = (int*)(smraw + SM_IND);
    int*     s_flg = (int*)(smraw + SM_FLG);

    const int tid  = threadIdx.x;
    const int tx   = tid & 15;     // 8 cols each
    const int ty   = tid >> 4;     // 4 row-pairs each (rows 8ty..8ty+7)
    const int w    = tid >> 5;
    const int lane = tid & 31;
    const int rb   = blockIdx.x * ROWS_BLK;

    // load X half2 image (dense [d][64] -> padded [d][68])
    const uint4* srcx = reinterpret_cast<const uint4*>(gXh + (size_t)blockIdx.x * 4096);
    #pragma unroll
    for (int j = 0; j < 4; j++) {
        int f = tid + j * 256;              // f < 1024 (uint4 units)
        int d = f >> 4, r4 = f & 15;
        *reinterpret_cast<uint4*>(&xh[d * 68 + r4 * 4]) = srcx[f];
    }
    #pragma unroll
    for (int j = 0; j < 4; j++) s_csq[tid + j * 256] = g_csq[tid + j * 256];

    float v1[8], v2[8];
    int   i1[8];
    #pragma unroll
    for (int s = 0; s < 8; s++) { v1[s] = -3.402823466e38f; v2[s] = -3.402823466e38f; i1[s] = 0; }

    const __half2 hz = __float2half2_rn(0.0f);

    for (int cc = 0; cc < CHUNKS; cc++) {
        __syncthreads();
        // load duplicated B chunk (dense [d][128] -> padded [d][132])
        const uint4* srcb = reinterpret_cast<const uint4*>(gBh + cc * 8192);
        #pragma unroll
        for (int j = 0; j < 8; j++) {
            int f = tid + j * 256;          // f < 2048 (uint4 units)
            int d = f >> 5, c4 = f & 31;
            *reinterpret_cast<uint4*>(&cs[d * 132 + c4 * 4]) = srcb[f];
        }
        __syncthreads();

        __half2 acc[4][8];
        #pragma unroll
        for (int rp = 0; rp < 4; rp++)
            #pragma unroll
            for (int c = 0; c < 8; c++) acc[rp][c] = hz;

        const __half2* xp = &xh[4 * ty];
        const __half2* cp = &cs[8 * tx];
        #pragma unroll 4
        for (int d = 0; d < 64; d++) {
            uint4 au  = *reinterpret_cast<const uint4*>(xp + d * 68);
            uint4 bu0 = *reinterpret_cast<const uint4*>(cp + d * 132);
            uint4 bu1 = *reinterpret_cast<const uint4*>(cp + d * 132 + 4);
            const __half2* a = reinterpret_cast<const __half2*>(&au);
            const __half2* b0 = reinterpret_cast<const __half2*>(&bu0);
            const __half2* b1 = reinterpret_cast<const __half2*>(&bu1);
            #pragma unroll
            for (int rp = 0; rp < 4; rp++) {
                acc[rp][0] = __hfma2(a[rp], b0[0], acc[rp][0]);
                acc[rp][1] = __hfma2(a[rp], b0[1], acc[rp][1]);
                acc[rp][2] = __hfma2(a[rp], b0[2], acc[rp][2]);
                acc[rp][3] = __hfma2(a[rp], b0[3], acc[rp][3]);
                acc[rp][4] = __hfma2(a[rp], b1[0], acc[rp][4]);
                acc[rp][5] = __hfma2(a[rp], b1[1], acc[rp][5]);
                acc[rp][6] = __hfma2(a[rp], b1[2], acc[rp][6]);
                acc[rp][7] = __hfma2(a[rp], b1[3], acc[rp][7]);
            }
        }

        // epilogue: acc.lo = row 8ty+2rp, acc.hi = row 8ty+2rp+1, col = cc*128+8tx+c
        #pragma unroll
        for (int c = 0; c < 8; c++) {
            int col = cc * 128 + 8 * tx + c;
            float cq = s_csq[col];
            #pragma unroll
            for (int rp = 0; rp < 4; rp++) {
                float2 f = __half22float2(acc[rp][c]);
                float s0 = fmaf(2.0f, f.x, -cq);
                float s1 = fmaf(2.0f, f.y, -cq);
                int e0 = rp * 2, e1 = rp * 2 + 1;
                if (s0 > v1[e0]) { v2[e0] = v1[e0]; v1[e0] = s0; i1[e0] = col; }
                else if (s0 > v2[e0]) v2[e0] = s0;
                if (s1 > v1[e1]) { v2[e1] = v1[e1]; v1[e1] = s1; i1[e1] = col; }
                else if (s1 > v2[e1]) v2[e1] = s1;
            }
        }
    }

    // reduce top-2 across the 16 tx-lanes sharing each row (xor 1,2,4,8 stays in half)
    #pragma unroll
    for (int s = 0; s < 8; s++) {
        float a1v = v1[s], a2v = v2[s];
        int   ai = i1[s];
        #pragma unroll
        for (int off = 1; off <= 8; off <<= 1) {
            float o1 = __shfl_xor_sync(0xffffffffu, a1v, off);
            float o2 = __shfl_xor_sync(0xffffffffu, a2v, off);
            int   oi = __shfl_xor_sync(0xffffffffu, ai, off);
            if (o1 > a1v || (o1 == a1v && oi < ai)) {
                a2v = fmaxf(a1v, o2); a1v = o1; ai = oi;
            } else {
                a2v = fmaxf(a2v, o1);
            }
        }
        if (tx == 0) {
            int row = 8 * ty + s;
            s_ind[row] = ai;
            s_flg[row] = (a1v - a2v <= TH_GAP) ? 1 : 0;
        }
    }
    __syncthreads();

    // fused segment sums: warp w handles 16 rows; lanes cover d and d+32
    #pragma unroll
    for (int t = 0; t < 16; t++) {
        int row = w * 16 + t;
        int k = s_ind[row];
        if (lane == 0) {
            g_ind[rb + row] = k;
            atomicAdd(&g_counts[k], 1);
            if (s_flg[row]) {
                int pos = atomicAdd(&g_nflag, 1);
                g_flag[pos] = rb + row;
            }
        }
        float xa = X[(size_t)(rb + row) * DIM + lane];
        float xb = X[(size_t)(rb + row) * DIM + 32 + lane];
        atomicAdd(&g_csum[k * 64 + lane],      xa);
        atomicAdd(&g_csum[k * 64 + 32 + lane], xb);
    }
}

// ---------------- exact fp32 recheck + correction -----------------------------
__global__ void __launch_bounds__(256)
recheck_kernel(const float* __restrict__ X) {
    __shared__ float fx[32 * 68];
    __shared__ float cz[64 * 68];
    const int tid  = threadIdx.x;
    const int w    = tid >> 5;
    const int lane = tid & 31;
    const int nf   = g_nflag;
    const float4* Ct4 = reinterpret_cast<const float4*>(g_Ct);

    for (int tile = blockIdx.x; tile * 32 < nf; tile += gridDim.x) {
        int base = tile * 32;
        int npts = nf - base; if (npts > 32) npts = 32;
        __syncthreads();
        for (int f = tid; f < npts * 16; f += 256) {
            int p = f >> 4, j = f & 15;
            int row = g_flag[base + p];
            *reinterpret_cast<float4*>(&fx[p * 68 + j * 4]) =
                *reinterpret_cast<const float4*>(X + (size_t)row * 64 + j * 4);
        }

        float bv[4];
        int   bk[4];
        #pragma unroll
        for (int ii = 0; ii < 4; ii++) { bv[ii] = -3.402823466e38f; bk[ii] = 0x7fffffff; }

        for (int ch = 0; ch < 16; ch++) {
            __syncthreads();
            #pragma unroll
            for (int i = 0; i < 4; i++) {
                int f = tid + i * 256;
                int n = f >> 4, j = f & 15;
                *reinterpret_cast<float4*>(&cz[n * 68 + j * 4]) = Ct4[(ch * 64 + n) * 16 + j];
            }
            __syncthreads();
            #pragma unroll
            for (int ii = 0; ii < 4; ii++) {
                int p = w * 4 + ii;
                if (p >= npts) continue;
                float s0 = 0.0f, s1 = 0.0f;
                #pragma unroll
                for (int d4 = 0; d4 < 16; d4++) {
                    float4 a  = *reinterpret_cast<const float4*>(&fx[p * 68 + d4 * 4]);
                    float4 b0 = *reinterpret_cast<const float4*>(&cz[lane * 68 + d4 * 4]);
                    float4 b1 = *reinterpret_cast<const float4*>(&cz[(lane + 32) * 68 + d4 * 4]);
                    s0 = fmaf(a.x, b0.x, s0); s0 = fmaf(a.y, b0.y, s0);
                    s0 = fmaf(a.z, b0.z, s0); s0 = fmaf(a.w, b0.w, s0);
                    s1 = fmaf(a.x, b1.x, s1); s1 = fmaf(a.y, b1.y, s1);
                    s1 = fmaf(a.z, b1.z, s1); s1 = fmaf(a.w, b1.w, s1);
                }
                int c0 = ch * 64 + lane;
                s0 = fmaf(2.0f, s0, -g_csq[c0]);
                s1 = fmaf(2.0f, s1, -g_csq[c0 + 32]);
                if (s0 > bv[ii]) { bv[ii] = s0; bk[ii] = c0; }
                if (s1 > bv[ii]) { bv[ii] = s1; bk[ii] = c0 + 32; }
            }
        }

        #pragma unroll
        for (int ii = 0; ii < 4; ii++) {
            int p = w * 4 + ii;
            float v = bv[ii];
            int   k = bk[ii];
            #pragma unroll
            for (int off = 16; off > 0; off >>= 1) {
                float ov = __shfl_xor_sync(0xffffffffu, v, off);
                int   ok = __shfl_xor_sync(0xffffffffu, k, off);
                if (ov > v || (ov == v && ok < k)) { v = ov; k = ok; }
            }
            if (p >= npts) continue;
            int row = g_flag[base + p];
            int oldk = g_ind[row];
            if (k != oldk) {
                if (lane == 0) {
                    g_ind[row] = k;
                    atomicAdd(&g_counts[oldk], -1);
                    atomicAdd(&g_counts[k], 1);
                }
                float xa = fx[p * 68 + lane];
                float xb = fx[p * 68 + 32 + lane];
                atomicAdd(&g_csum[oldk * 64 + lane], -xa);
                atomicAdd(&g_csum[k * 64 + lane],     xa);
                atomicAdd(&g_csum[oldk * 64 + 32 + lane], -xb);
                atomicAdd(&g_csum[k * 64 + 32 + lane],     xb);
            }
        }
    }
}

// ---------------- EMA update + normalize (parallel) ---------------------------
__global__ void update2_kernel(const float* __restrict__ cluster_size,
                               const float* __restrict__ cavg) {
    int i = blockIdx.x * blockDim.x + threadIdx.x;
    int k = i >> 6;
    int d = i & 63;
    float n = 0.99f * g_sum_cs + 0.01f * (float)N_PTS;
    float csz = 0.99f * cluster_size[k] + 0.01f * (float)g_counts[k];
    float cs = (csz + 1e-5f) / (n + (float)KCENT * 1e-5f) * n;
    float avg_new = 0.99f * cavg[d * KCENT + k] + 0.01f * g_csum[i];
    g_cnew[i] = avg_new / cs;
}

// ---------------- gather + loss -------------------------------------------------
__global__ void gather_kernel(const float* __restrict__ X, float* __restrict__ out) {
    float lsum = 0.0f;
    const int stride = gridDim.x * blockDim.x;
    const float4* Xv = reinterpret_cast<const float4*>(X);
    float4* Ov = reinterpret_cast<float4*>(out);
    for (int i = blockIdx.x * blockDim.x + threadIdx.x; i < N_PTS * DIM / 4; i += stride) {
        int n  = i >> 4;
        int d4 = (i & 15) * 4;
        float4 q = *reinterpret_cast<const float4*>(&g_cnew[g_ind[n] * 64 + d4]);
        float4 x = Xv[i];
        float4 o;
        o.x = x.x + (q.x - x.x);
        o.y = x.y + (q.y - x.y);
        o.z = x.z + (q.z - x.z);
        o.w = x.w + (q.w - x.w);
        Ov[i] = o;
        float dx = x.x - q.x, dy = x.y - q.y, dz = x.z - q.z, dw = x.w - q.w;
        lsum = fmaf(dx, dx, lsum);
        lsum = fmaf(dy, dy, lsum);
        lsum = fmaf(dz, dz, lsum);
        lsum = fmaf(dw, dw, lsum);
    }
    __shared__ float red[256];
    red[threadIdx.x] = lsum;
    __syncthreads();
    #pragma unroll
    for (int s = 128; s > 0; s >>= 1) {
        if (threadIdx.x < s) red[threadIdx.x] += red[threadIdx.x + s];
        __syncthreads();
    }
    if (threadIdx.x == 0) atomicAdd(&g_loss, red[0]);
}

__global__ void finalize_kernel(float* out, int out_size) {
    float loss = g_loss * (1.0f / 8388608.0f);   // 1/(N*D), exact
    for (int i = N_PTS * DIM; i < out_size; i++) out[i] = loss;
}

// -------------------------------------------------------------------------------
extern "C" void kernel_launch(void* const* d_in, const int* in_sizes, int n_in,
                              void* d_out, int out_size) {
    const float* x             = (const float*)d_in[0];  // [N, D]
    const float* centroids     = (const float*)d_in[1];  // [D, K]
    const float* cluster_size  = (const float*)d_in[2];  // [K]
    const float* centroids_avg = (const float*)d_in[3];  // [D, K]
    float* out = (float*)d_out;

    cudaFuncSetAttribute(assign_kernel,
                         cudaFuncAttributeMaxDynamicSharedMemorySize, SM_BYTES);

    zero_kernel<<<(KCENT * DIM + 255) / 256, 256>>>();
    csq_kernel<<<KCENT / 256, 256>>>(centroids);
    sumcs_kernel<<<1, 1024>>>(cluster_size);
    prep_Ct<<<dim3(32, 2), 256>>>(centroids);
    prep_Xh<<<ASSIGN_BLOCKS, 256>>>(x);
    prep_Bh<<<(CHUNKS * 64 * 128 + 255) / 256, 256>>>(centroids);
    assign_kernel<<<ASSIGN_BLOCKS, 256, SM_BYTES>>>(x);
    recheck_kernel<<<256, 256>>>(x);
    update2_kernel<<<KCENT * DIM / 256, 256>>>(cluster_size, centroids_avg);
    gather_kernel<<<2048, 256>>>(x, out);
    finalize_kernel<<<1, 1>>>(out, out_size);
}

// round 10
// speedup vs baseline: 1.6245x; 1.6245x over previous
#include <cuda_runtime.h>
#include <cstdint>

// Problem constants
#define N_PTS 131072
#define DIM   64
#define KCENT 1024

#define CH_F (64 * 132)      // floats per padded B chunk image in smem

typedef unsigned long long u64;

// Scratch (device globals — no allocation allowed)
__device__ float g_csq[KCENT];
__device__ int   g_ind[N_PTS];
__device__ int   g_counts[KCENT];
__device__ float g_csum[KCENT * DIM];   // [k][d] segment sums of x
__device__ float g_cnew[KCENT * DIM];   // [k][d] updated codebook
__device__ float g_loss;
__device__ float g_sum_cs;

// ---- packed f32x2 helpers (Blackwell 2-wide fp32 datapath) ------------------
__device__ __forceinline__ u64 ffma2(u64 a, u64 b, u64 c) {
    u64 d;
    asm("fma.rn.f32x2 %0, %1, %2, %3;" : "=l"(d) : "l"(a), "l"(b), "l"(c));
    return d;
}
__device__ __forceinline__ u64 pack2(float lo, float hi) {
    u64 d; asm("mov.b64 %0, {%1, %2};" : "=l"(d) : "f"(lo), "f"(hi)); return d;
}
__device__ __forceinline__ void unpack2(u64 v, float& lo, float& hi) {
    asm("mov.b64 {%0, %1}, %2;" : "=f"(lo), "=f"(hi) : "l"(v));
}
__device__ __forceinline__ uint32_t smem_u32(const void* p) {
    uint32_t a;
    asm("{ .reg .u64 t; cvta.to.shared.u64 t, %1; cvt.u32.u64 %0, t; }"
        : "=r"(a) : "l"(p));
    return a;
}

// ---------------------------------------------------------------------------
// Zero the per-launch scratch
// ---------------------------------------------------------------------------
__global__ void zero_kernel() {
    int i = blockIdx.x * blockDim.x + threadIdx.x;
    if (i < KCENT * DIM) g_csum[i] = 0.0f;
    if (i < KCENT)       g_counts[i] = 0;
    if (i == 0)          g_loss = 0.0f;
}

// ---------------------------------------------------------------------------
// c_sq[k] = sum_d centroids[d][k]^2   (centroids is [D][K] row-major)
// ---------------------------------------------------------------------------
__global__ void csq_kernel(const float* __restrict__ C) {
    int k = blockIdx.x * blockDim.x + threadIdx.x;
    if (k < KCENT) {
        float s = 0.0f;
        #pragma unroll
        for (int d = 0; d < DIM; d++) {
            float c = C[d * KCENT + k];
            s = fmaf(c, c, s);
        }
        g_csq[k] = s;
    }
}

// ---------------------------------------------------------------------------
// sum(cluster_size) — one small block, feeds the update kernel
// ---------------------------------------------------------------------------
__global__ void sumcs_kernel(const float* __restrict__ cluster_size) {
    __shared__ float red[1024];
    int k = threadIdx.x;
    red[k] = cluster_size[k];
    __syncthreads();
    #pragma unroll
    for (int s = 512; s > 0; s >>= 1) {
        if (k < s) red[k] += red[k + s];
        __syncthreads();
    }
    if (k == 0) g_sum_cs = red[0];
}

// ---------------------------------------------------------------------------
// Assignment: per-row argmax_k (2*x.c_k - csq[k])  == argmin distance.
// R2 structure verbatim; ONLY delta: B chunks arrive via cp.async double
// buffer so LDG latency is hidden under compute, one barrier per chunk.
// ---------------------------------------------------------------------------
__device__ __forceinline__ void issue_chunk(uint32_t dst, const float* __restrict__ C,
                                            int cc, int tid) {
    #pragma unroll
    for (int j = 0; j < 8; j++) {
        int f = tid + j * 256;       // f < 2048 float4 per chunk
        int d  = f >> 5;
        int c4 = f & 31;
        const float* src = C + d * KCENT + cc * 128 + c4 * 4;
        asm volatile("cp.async.cg.shared.global [%0], [%1], 16;"
                     :: "r"(dst + (uint32_t)(d * 132 + c4 * 4) * 4u), "l"(src));
    }
}

__global__ void __launch_bounds__(256, 2)
assign_kernel(const float* __restrict__ X, const float* __restrict__ C) {
    extern __shared__ __align__(16) float smem[];
    float* xs  = smem;                 // [64][132] x tile, transposed: xs[d][r]
    float* cs0 = smem + CH_F;          // B chunk buffer 0
    float* cs1 = smem + 2 * CH_F;      // B chunk buffer 1
    int*   s_ind = (int*)(smem + 3 * CH_F);   // [128]

    const int tid = threadIdx.x;
    const int tx = tid & 15;
    const int ty = tid >> 4;
    const int rb = blockIdx.x * 128;

    const uint32_t cs0a = smem_u32(cs0);
    const uint32_t cs1a = smem_u32(cs1);

    // prologue: async-load chunk 0 into buffer 0
    issue_chunk(cs0a, C, 0, tid);
    asm volatile("cp.async.commit_group;");

    // Load x tile [128 rows x 64] transposed into smem
    const float4* Xv = reinterpret_cast<const float4*>(X + (size_t)rb * DIM);
    #pragma unroll
    for (int f = tid; f < 2048; f += 256) {
        float4 v = Xv[f];
        int r = f >> 4;
        int d = (f & 15) * 4;
        xs[(d + 0) * 132 + r] = v.x;
        xs[(d + 1) * 132 + r] = v.y;
        xs[(d + 2) * 132 + r] = v.z;
        xs[(d + 3) * 132 + r] = v.w;
    }

    float bestv[8];
    int   besti[8];
    #pragma unroll
    for (int i = 0; i < 8; i++) { bestv[i] = -3.402823466e38f; besti[i] = 0; }

    const int r0 = ty * 4;   // rows r0..r0+3 and 64+r0..64+r0+3
    const int c0 = tx * 4;   // cols c0..c0+3 and 64+c0..64+c0+3 (within chunk)

    for (int kc = 0; kc < 8; kc++) {
        asm volatile("cp.async.wait_group 0;");
        __syncthreads();
        // prefetch next chunk into the other buffer (lands during compute)
        if (kc < 7) {
            issue_chunk((kc & 1) ? cs0a : cs1a, C, kc + 1, tid);
            asm volatile("cp.async.commit_group;");
        }
        const float* cs = (kc & 1) ? cs1 : cs0;

        // accp[i][jj]: row i (8), packed column pair jj (4): cols 2jj, 2jj+1
        u64 accp[8][4];
        #pragma unroll
        for (int i = 0; i < 8; i++)
            #pragma unroll
            for (int jj = 0; jj < 4; jj++) accp[i][jj] = 0ULL;

        #pragma unroll 4
        for (int d = 0; d < 64; d++) {
            float4 a0 = *reinterpret_cast<const float4*>(&xs[d * 132 + r0]);
            float4 a1 = *reinterpret_cast<const float4*>(&xs[d * 132 + 64 + r0]);
            float4 b0 = *reinterpret_cast<const float4*>(&cs[d * 132 + c0]);
            float4 b1 = *reinterpret_cast<const float4*>(&cs[d * 132 + 64 + c0]);
            u64 bp[4];
            bp[0] = pack2(b0.x, b0.y);
            bp[1] = pack2(b0.z, b0.w);
            bp[2] = pack2(b1.x, b1.y);
            bp[3] = pack2(b1.z, b1.w);
            float a[8] = {a0.x, a0.y, a0.z, a0.w, a1.x, a1.y, a1.z, a1.w};
            #pragma unroll
            for (int i = 0; i < 8; i++) {
                u64 ad = pack2(a[i], a[i]);
                #pragma unroll
                for (int jj = 0; jj < 4; jj++)
                    accp[i][jj] = ffma2(ad, bp[jj], accp[i][jj]);
            }
        }

        // Epilogue: score = 2*dot - csq; running argmax, visiting columns in
        // ascending order per thread (strict > preserves first-min tiebreak)
        #pragma unroll
        for (int jj = 0; jj < 4; jj++) {
            int base = kc * 128 + ((jj < 2) ? (c0 + jj * 2) : (64 + c0 + (jj - 2) * 2));
            float cq0 = g_csq[base];
            float cq1 = g_csq[base + 1];
            #pragma unroll
            for (int i = 0; i < 8; i++) {
                float lo, hi;
                unpack2(accp[i][jj], lo, hi);
                float s0 = fmaf(2.0f, lo, -cq0);
                float s1 = fmaf(2.0f, hi, -cq1);
                if (s0 > bestv[i]) { bestv[i] = s0; besti[i] = base; }
                if (s1 > bestv[i]) { bestv[i] = s1; besti[i] = base + 1; }
            }
        }
    }

    // Reduce across the 16 tx-threads sharing each row group (half-warp xor).
    #pragma unroll
    for (int i = 0; i < 8; i++) {
        float v = bestv[i];
        int  ix = besti[i];
        #pragma unroll
        for (int off = 8; off > 0; off >>= 1) {
            float ov = __shfl_xor_sync(0xffffffffu, v, off);
            int   oi = __shfl_xor_sync(0xffffffffu, ix, off);
            if (ov > v || (ov == v && oi < ix)) { v = ov; ix = oi; }
        }
        if (tx == 0) {
            int row = (i < 4) ? (r0 + i) : (64 + r0 + (i - 4));
            s_ind[row] = ix;
        }
    }
    __syncthreads();

    // Fused segment sums: each warp handles 16 rows; lanes cover d and d+32.
    const int lane = tid & 31;
    const int w    = tid >> 5;
    #pragma unroll
    for (int t = 0; t < 16; t++) {
        int row = w * 16 + t;
        int k = s_ind[row];
        if (lane == 0) {
            g_ind[rb + row] = k;
            atomicAdd(&g_counts[k], 1);
        }
        atomicAdd(&g_csum[k * 64 + lane],      xs[lane * 132 + row]);
        atomicAdd(&g_csum[k * 64 + 32 + lane], xs[(32 + lane) * 132 + row]);
    }
}

// ---------------------------------------------------------------------------
// EMA update + Laplace smoothing + codebook normalize — fully parallel.
// n = 0.99*sum(cluster_size) + 0.01*N  (sum of counts == N exactly)
// ---------------------------------------------------------------------------
__global__ void update2_kernel(const float* __restrict__ cluster_size,
                               const float* __restrict__ cavg) {
    int i = blockIdx.x * blockDim.x + threadIdx.x;   // 65536 threads
    int k = i >> 6;
    int d = i & 63;
    float n = 0.99f * g_sum_cs + 0.01f * (float)N_PTS;
    float csz = 0.99f * cluster_size[k] + 0.01f * (float)g_counts[k];
    float cs = (csz + 1e-5f) / (n + (float)KCENT * 1e-5f) * n;
    float avg_new = 0.99f * cavg[d * KCENT + k] + 0.01f * g_csum[i];
    g_cnew[i] = avg_new / cs;
}

// ---------------------------------------------------------------------------
// Gather quantized vectors + loss partial sums (float4 vectorized).
// ---------------------------------------------------------------------------
__global__ void gather_kernel(const float* __restrict__ X, float* __restrict__ out) {
    float lsum = 0.0f;
    const int stride = gridDim.x * blockDim.x;
    const float4* Xv = reinterpret_cast<const float4*>(X);
    float4* Ov = reinterpret_cast<float4*>(out);
    for (int i = blockIdx.x * blockDim.x + threadIdx.x; i < N_PTS * DIM / 4; i += stride) {
        int n  = i >> 4;
        int d4 = (i & 15) * 4;
        float4 q = *reinterpret_cast<const float4*>(&g_cnew[g_ind[n] * 64 + d4]);
        float4 x = Xv[i];
        float4 o;
        o.x = x.x + (q.x - x.x);
        o.y = x.y + (q.y - x.y);
        o.z = x.z + (q.z - x.z);
        o.w = x.w + (q.w - x.w);
        Ov[i] = o;
        float dx = x.x - q.x, dy = x.y - q.y, dz = x.z - q.z, dw = x.w - q.w;
        lsum = fmaf(dx, dx, lsum);
        lsum = fmaf(dy, dy, lsum);
        lsum = fmaf(dz, dz, lsum);
        lsum = fmaf(dw, dw, lsum);
    }
    __shared__ float red[256];
    red[threadIdx.x] = lsum;
    __syncthreads();
    #pragma unroll
    for (int s = 128; s > 0; s >>= 1) {
        if (threadIdx.x < s) red[threadIdx.x] += red[threadIdx.x + s];
        __syncthreads();
    }
    if (threadIdx.x == 0) atomicAdd(&g_loss, red[0]);
}

// Final scalar: mean loss into the tail of the output buffer (if present).
__global__ void finalize_kernel(float* out, int out_size) {
    float loss = g_loss * (1.0f / 8388608.0f);   // 1/(N*D), exact power of 2
    for (int i = N_PTS * DIM; i < out_size; i++) out[i] = loss;
}

// ---------------------------------------------------------------------------
extern "C" void kernel_launch(void* const* d_in, const int* in_sizes, int n_in,
                              void* d_out, int out_size) {
    const float* x             = (const float*)d_in[0];  // [N, D]
    const float* centroids     = (const float*)d_in[1];  // [D, K]
    const float* cluster_size  = (const float*)d_in[2];  // [K]
    const float* centroids_avg = (const float*)d_in[3];  // [D, K]
    float* out = (float*)d_out;

    const int smem_bytes = (3 * CH_F + 128) * (int)sizeof(float);  // 101,888+512
    cudaFuncSetAttribute(assign_kernel,
                         cudaFuncAttributeMaxDynamicSharedMemorySize, smem_bytes);

    zero_kernel<<<(KCENT * DIM + 255) / 256, 256>>>();
    csq_kernel<<<KCENT / 256, 256>>>(centroids);
    sumcs_kernel<<<1, 1024>>>(cluster_size);
    assign_kernel<<<N_PTS / 128, 256, smem_bytes>>>(x, centroids);
    update2_kernel<<<KCENT * DIM / 256, 256>>>(cluster_size, centroids_avg);
    gather_kernel<<<2048, 256>>>(x, out);
    finalize_kernel<<<1, 1>>>(out, out_size);
}

// round 11
// speedup vs baseline: 1.6972x; 1.0448x over previous
#include <cuda_runtime.h>
#include <cstdint>

// Problem constants
#define N_PTS 131072
#define DIM   64
#define KCENT 1024

typedef unsigned long long u64;

// Scratch (device globals — no allocation allowed)
__device__ float g_csq[KCENT];
__device__ int   g_ind[N_PTS];
__device__ int   g_counts[KCENT];
__device__ float g_csum[KCENT * DIM];   // [k][d] segment sums of x
__device__ float g_cnew[KCENT * DIM];   // [k][d] updated codebook
__device__ float g_loss;

// ---- packed f32x2 helpers (Blackwell 2-wide fp32 datapath) ------------------
__device__ __forceinline__ u64 ffma2(u64 a, u64 b, u64 c) {
    u64 d;
    asm("fma.rn.f32x2 %0, %1, %2, %3;" : "=l"(d) : "l"(a), "l"(b), "l"(c));
    return d;
}
__device__ __forceinline__ u64 pack2(float lo, float hi) {
    u64 d; asm("mov.b64 %0, {%1, %2};" : "=l"(d) : "f"(lo), "f"(hi)); return d;
}
__device__ __forceinline__ void unpack2(u64 v, float& lo, float& hi) {
    asm("mov.b64 {%0, %1}, %2;" : "=f"(lo), "=f"(hi) : "l"(v));
}

// ---------------------------------------------------------------------------
// Fused prep: zero csum/counts/loss + csq[k] = sum_d C[d][k]^2
// grid 256 x 256 = 65536 threads (exactly KCENT*DIM)
// ---------------------------------------------------------------------------
__global__ void prep_kernel(const float* __restrict__ C) {
    int i = blockIdx.x * blockDim.x + threadIdx.x;
    g_csum[i] = 0.0f;
    if (i < KCENT) {
        g_counts[i] = 0;
        float s = 0.0f;
        #pragma unroll
        for (int d = 0; d < DIM; d++) {
            float c = C[d * KCENT + i];
            s = fmaf(c, c, s);
        }
        g_csq[i] = s;
    }
    if (i == 0) g_loss = 0.0f;
}

// ---------------------------------------------------------------------------
// Assignment: per-row argmax_k (2*x.c_k - csq[k])  == argmin distance.
// 128-row x-tile per block, loops K in 8 chunks of 128 columns.
// 256 threads, 8x8 register microtile done as 8x4 packed f32x2 accumulators.
// Epilogue: half-warp argmax reduction, then fused segment-sum atomics.
// (R2 kernel verbatim — measured at the FFMA2 rt=3 roofline.)
// ---------------------------------------------------------------------------
__global__ void __launch_bounds__(256, 2)
assign_kernel(const float* __restrict__ X, const float* __restrict__ C) {
    extern __shared__ float smem[];
    float* xs = smem;                 // [64][132] x tile, transposed: xs[d][r]
    float* cs = smem + 64 * 132;      // [64][132] C chunk: cs[d][c]
    int*   s_ind = (int*)(smem + 2 * 64 * 132);   // [128]

    const int tid = threadIdx.x;
    const int tx = tid & 15;
    const int ty = tid >> 4;
    const int rb = blockIdx.x * 128;

    // Load x tile [128 rows x 64] transposed into smem
    const float4* Xv = reinterpret_cast<const float4*>(X + (size_t)rb * DIM);
    #pragma unroll
    for (int f = tid; f < 2048; f += 256) {
        float4 v = Xv[f];
        int r = f >> 4;
        int d = (f & 15) * 4;
        xs[(d + 0) * 132 + r] = v.x;
        xs[(d + 1) * 132 + r] = v.y;
        xs[(d + 2) * 132 + r] = v.z;
        xs[(d + 3) * 132 + r] = v.w;
    }

    float bestv[8];
    int   besti[8];
    #pragma unroll
    for (int i = 0; i < 8; i++) { bestv[i] = -3.402823466e38f; besti[i] = 0; }

    const int r0 = ty * 4;   // rows r0..r0+3 and 64+r0..64+r0+3
    const int c0 = tx * 4;   // cols c0..c0+3 and 64+c0..64+c0+3 (within chunk)

    for (int kc = 0; kc < 8; kc++) {
        __syncthreads();
        // Load C chunk [64 x 128], float4, coalesced
        #pragma unroll
        for (int f = tid; f < 2048; f += 256) {
            int d  = f >> 5;
            int c4 = f & 31;
            float4 v = *reinterpret_cast<const float4*>(C + d * KCENT + kc * 128 + c4 * 4);
            *reinterpret_cast<float4*>(&cs[d * 132 + c4 * 4]) = v;
        }
        __syncthreads();

        // accp[i][jj]: row i (8), packed column pair jj (4): cols 2jj, 2jj+1
        u64 accp[8][4];
        #pragma unroll
        for (int i = 0; i < 8; i++)
            #pragma unroll
            for (int jj = 0; jj < 4; jj++) accp[i][jj] = 0ULL;

        #pragma unroll 4
        for (int d = 0; d < 64; d++) {
            float4 a0 = *reinterpret_cast<const float4*>(&xs[d * 132 + r0]);
            float4 a1 = *reinterpret_cast<const float4*>(&xs[d * 132 + 64 + r0]);
            float4 b0 = *reinterpret_cast<const float4*>(&cs[d * 132 + c0]);
            float4 b1 = *reinterpret_cast<const float4*>(&cs[d * 132 + 64 + c0]);
            u64 bp[4];
            bp[0] = pack2(b0.x, b0.y);
            bp[1] = pack2(b0.z, b0.w);
            bp[2] = pack2(b1.x, b1.y);
            bp[3] = pack2(b1.z, b1.w);
            float a[8] = {a0.x, a0.y, a0.z, a0.w, a1.x, a1.y, a1.z, a1.w};
            #pragma unroll
            for (int i = 0; i < 8; i++) {
                u64 ad = pack2(a[i], a[i]);
                #pragma unroll
                for (int jj = 0; jj < 4; jj++)
                    accp[i][jj] = ffma2(ad, bp[jj], accp[i][jj]);
            }
        }

        // Epilogue: score = 2*dot - csq; running argmax, visiting columns in
        // ascending order per thread (strict > preserves first-min tiebreak)
        #pragma unroll
        for (int jj = 0; jj < 4; jj++) {
            int base = kc * 128 + ((jj < 2) ? (c0 + jj * 2) : (64 + c0 + (jj - 2) * 2));
            float cq0 = g_csq[base];
            float cq1 = g_csq[base + 1];
            #pragma unroll
            for (int i = 0; i < 8; i++) {
                float lo, hi;
                unpack2(accp[i][jj], lo, hi);
                float s0 = fmaf(2.0f, lo, -cq0);
                float s1 = fmaf(2.0f, hi, -cq1);
                if (s0 > bestv[i]) { bestv[i] = s0; besti[i] = base; }
                if (s1 > bestv[i]) { bestv[i] = s1; besti[i] = base + 1; }
            }
        }
    }

    // Reduce across the 16 tx-threads sharing each row group (half-warp xor).
    #pragma unroll
    for (int i = 0; i < 8; i++) {
        float v = bestv[i];
        int  ix = besti[i];
        #pragma unroll
        for (int off = 8; off > 0; off >>= 1) {
            float ov = __shfl_xor_sync(0xffffffffu, v, off);
            int   oi = __shfl_xor_sync(0xffffffffu, ix, off);
            if (ov > v || (ov == v && oi < ix)) { v = ov; ix = oi; }
        }
        if (tx == 0) {
            int row = (i < 4) ? (r0 + i) : (64 + r0 + (i - 4));
            s_ind[row] = ix;
        }
    }
    __syncthreads();

    // Fused segment sums: each warp handles 16 rows; lanes cover d and d+32.
    const int lane = tid & 31;
    const int w    = tid >> 5;
    #pragma unroll
    for (int t = 0; t < 16; t++) {
        int row = w * 16 + t;
        int k = s_ind[row];
        if (lane == 0) {
            g_ind[rb + row] = k;
            atomicAdd(&g_counts[k], 1);
        }
        atomicAdd(&g_csum[k * 64 + lane],      xs[lane * 132 + row]);
        atomicAdd(&g_csum[k * 64 + 32 + lane], xs[(32 + lane) * 132 + row]);
    }
}

// ---------------------------------------------------------------------------
// EMA update + Laplace smoothing + codebook normalize — fully parallel.
// Per-block reduction of cluster_size (4 KB, L2-resident) replaces the
// separate sumcs kernel. n = 0.99*sum(cluster_size) + 0.01*N (counts sum = N).
// ---------------------------------------------------------------------------
__global__ void update2_kernel(const float* __restrict__ cluster_size,
                               const float* __restrict__ cavg) {
    __shared__ float red[256];
    const int t = threadIdx.x;
    float s = cluster_size[t] + cluster_size[t + 256]
            + cluster_size[t + 512] + cluster_size[t + 768];
    red[t] = s;
    __syncthreads();
    #pragma unroll
    for (int st = 128; st > 0; st >>= 1) {
        if (t < st) red[t] += red[t + st];
        __syncthreads();
    }
    float n = 0.99f * red[0] + 0.01f * (float)N_PTS;

    int i = blockIdx.x * blockDim.x + t;   // 65536 threads
    int k = i >> 6;
    int d = i & 63;
    float csz = 0.99f * cluster_size[k] + 0.01f * (float)g_counts[k];
    float cs = (csz + 1e-5f) / (n + (float)KCENT * 1e-5f) * n;
    float avg_new = 0.99f * cavg[d * KCENT + k] + 0.01f * g_csum[i];
    g_cnew[i] = avg_new / cs;
}

// ---------------------------------------------------------------------------
// Gather quantized vectors + loss partial sums (float4 vectorized).
// ---------------------------------------------------------------------------
__global__ void gather_kernel(const float* __restrict__ X, float* __restrict__ out) {
    float lsum = 0.0f;
    const int stride = gridDim.x * blockDim.x;
    const float4* Xv = reinterpret_cast<const float4*>(X);
    float4* Ov = reinterpret_cast<float4*>(out);
    for (int i = blockIdx.x * blockDim.x + threadIdx.x; i < N_PTS * DIM / 4; i += stride) {
        int n  = i >> 4;
        int d4 = (i & 15) * 4;
        float4 q = *reinterpret_cast<const float4*>(&g_cnew[g_ind[n] * 64 + d4]);
        float4 x = Xv[i];
        float4 o;
        o.x = x.x + (q.x - x.x);
        o.y = x.y + (q.y - x.y);
        o.z = x.z + (q.z - x.z);
        o.w = x.w + (q.w - x.w);
        Ov[i] = o;
        float dx = x.x - q.x, dy = x.y - q.y, dz = x.z - q.z, dw = x.w - q.w;
        lsum = fmaf(dx, dx, lsum);
        lsum = fmaf(dy, dy, lsum);
        lsum = fmaf(dz, dz, lsum);
        lsum = fmaf(dw, dw, lsum);
    }
    __shared__ float red[256];
    red[threadIdx.x] = lsum;
    __syncthreads();
    #pragma unroll
    for (int s = 128; s > 0; s >>= 1) {
        if (threadIdx.x < s) red[threadIdx.x] += red[threadIdx.x + s];
        __syncthreads();
    }
    if (threadIdx.x == 0) atomicAdd(&g_loss, red[0]);
}

// Final scalar: mean loss into the tail of the output buffer (if present).
__global__ void finalize_kernel(float* out, int out_size) {
    float loss = g_loss * (1.0f / 8388608.0f);   // 1/(N*D), exact power of 2
    for (int i = N_PTS * DIM; i < out_size; i++) out[i] = loss;
}

// ---------------------------------------------------------------------------
extern "C" void kernel_launch(void* const* d_in, const int* in_sizes, int n_in,
                              void* d_out, int out_size) {
    const float* x             = (const float*)d_in[0];  // [N, D]
    const float* centroids     = (const float*)d_in[1];  // [D, K]
    const float* cluster_size  = (const float*)d_in[2];  // [K]
    const float* centroids_avg = (const float*)d_in[3];  // [D, K]
    float* out = (float*)d_out;

    const int smem_bytes = (2 * 64 * 132 + 128) * (int)sizeof(float);  // 68096
    cudaFuncSetAttribute(assign_kernel,
                         cudaFuncAttributeMaxDynamicSharedMemorySize, smem_bytes);

    prep_kernel<<<KCENT * DIM / 256, 256>>>(centroids);
    assign_kernel<<<N_PTS / 128, 256, smem_bytes>>>(x, centroids);
    update2_kernel<<<KCENT * DIM / 256, 256>>>(cluster_size, centroids_avg);
    gather_kernel<<<2048, 256>>>(x, out);
    finalize_kernel<<<1, 1>>>(out, out_size);
}